// round 1
// baseline (speedup 1.0000x reference)
#include <cuda_runtime.h>
#include <math.h>

// Problem constants (fixed shapes)
#define NB   4
#define LQL  2048
#define DM   1024
#define HH   16
#define PP   64
#define MROWS (NB*LQL)        // 8192
#define EPSBN 1e-5f

// ---------------- scratch (device globals: allocation-free) ----------------
__device__ float gQ  [MROWS * DM];
__device__ float gK  [MROWS * DM];
__device__ float gV  [MROWS * DM];
__device__ float gRes[MROWS * DM];
__device__ float gPartS[64 * DM];
__device__ float gPartQ[64 * DM];
__device__ float gColA[DM];
__device__ float gColB[DM];

// ---------------------------------------------------------------------------
// SGEMM NT: C[m][n] = sum_k A[m][k] * B[n][k]
// A: [8192,1024] row-major, B: [1024,1024] row-major ([out][in] = W)
// Block tile 64x64, BK=32, 256 threads, 4x4 micro-tile per thread.
// ---------------------------------------------------------------------------
__global__ void __launch_bounds__(256) sgemm_nt(const float* __restrict__ A,
                                                const float* __restrict__ B,
                                                int which)
{
    float* __restrict__ C = (which == 0) ? gQ : ((which == 1) ? gK : gV);

    __shared__ float As[64][65];
    __shared__ float Bs[64][65];

    const int tid = threadIdx.x;
    const int tx  = tid & 15;
    const int ty  = tid >> 4;
    const int m0  = blockIdx.y * 64;
    const int n0  = blockIdx.x * 64;
    const int K   = DM;

    float acc[4][4] = {};

    for (int k0 = 0; k0 < K; k0 += 32) {
        #pragma unroll
        for (int it = 0; it < 2; ++it) {
            int r = (tid >> 3) + it * 32;   // 0..63
            int c = (tid & 7) << 2;         // 0..28
            float4 a = *(const float4*)(A + (size_t)(m0 + r) * K + k0 + c);
            As[r][c + 0] = a.x; As[r][c + 1] = a.y;
            As[r][c + 2] = a.z; As[r][c + 3] = a.w;
            float4 b = *(const float4*)(B + (size_t)(n0 + r) * K + k0 + c);
            Bs[r][c + 0] = b.x; Bs[r][c + 1] = b.y;
            Bs[r][c + 2] = b.z; Bs[r][c + 3] = b.w;
        }
        __syncthreads();

        #pragma unroll 8
        for (int kk = 0; kk < 32; ++kk) {
            float a[4], b[4];
            #pragma unroll
            for (int i = 0; i < 4; ++i) a[i] = As[ty * 4 + i][kk];
            #pragma unroll
            for (int j = 0; j < 4; ++j) b[j] = Bs[tx * 4 + j][kk];
            #pragma unroll
            for (int i = 0; i < 4; ++i)
                #pragma unroll
                for (int j = 0; j < 4; ++j)
                    acc[i][j] += a[i] * b[j];
        }
        __syncthreads();
    }

    #pragma unroll
    for (int i = 0; i < 4; ++i) {
        const size_t row = (size_t)(m0 + ty * 4 + i);
        #pragma unroll
        for (int j = 0; j < 4; ++j)
            C[row * DM + n0 + tx * 4 + j] = acc[i][j];
    }
}

// ---------------------------------------------------------------------------
// Causal flash attention, one (n, h, 64-row q-tile) per block.
// Qs/Ss plain [64][64]; KV tile uses an additive swizzle so both the
// row-major K reads (S = Q K^T) and the column reads (O += P V) land on
// 8 banks / 2-way worst case. Total static smem = exactly 48 KB.
// ---------------------------------------------------------------------------
#define KVS(r, c) KVs[((r) << 6) + (((c) + (r)) & 63)]

__global__ void __launch_bounds__(256) attn_kernel(const float* __restrict__ query)
{
    __shared__ float Qs[64][64];
    __shared__ float KVs[64 * 64];
    __shared__ float Ss[64][64];

    const int tid = threadIdx.x;
    const int tx  = tid & 15;
    const int ty  = tid >> 4;
    const int qt  = blockIdx.x;   // 0..31
    const int h   = blockIdx.y;   // 0..15
    const int n   = blockIdx.z;   // 0..3

    const size_t nbase = (size_t)n * LQL * DM;
    const float* Qb = gQ + nbase + (size_t)qt * 64 * DM + h * PP;

    // Load Q tile [64 rows x 64 cols]
    #pragma unroll
    for (int v = 0; v < 4; ++v) {
        int lin = v * 256 + tid;
        int r = lin >> 4;
        int c = (lin & 15) << 2;
        float4 q4 = *(const float4*)(Qb + (size_t)r * DM + c);
        Qs[r][c + 0] = q4.x; Qs[r][c + 1] = q4.y;
        Qs[r][c + 2] = q4.z; Qs[r][c + 3] = q4.w;
    }

    float o[4][4] = {};
    float mreg[4], lreg[4];
    #pragma unroll
    for (int i = 0; i < 4; ++i) { mreg[i] = -INFINITY; lreg[i] = 0.f; }

    for (int kt = 0; kt <= qt; ++kt) {
        __syncthreads();  // prior PV reads done (and Q tile visible on iter 0)

        // Load K tile into KVs
        const float* Kb = gK + nbase + (size_t)kt * 64 * DM + h * PP;
        #pragma unroll
        for (int v = 0; v < 4; ++v) {
            int lin = v * 256 + tid;
            int r = lin >> 4;
            int c = (lin & 15) << 2;
            float4 k4 = *(const float4*)(Kb + (size_t)r * DM + c);
            KVS(r, c + 0) = k4.x; KVS(r, c + 1) = k4.y;
            KVS(r, c + 2) = k4.z; KVS(r, c + 3) = k4.w;
        }
        __syncthreads();

        // S = Q K^T  (4x4 per thread)
        float s[4][4] = {};
        #pragma unroll 8
        for (int p = 0; p < 64; ++p) {
            float a[4], b[4];
            #pragma unroll
            for (int i = 0; i < 4; ++i) a[i] = Qs[ty * 4 + i][p];
            #pragma unroll
            for (int j = 0; j < 4; ++j) b[j] = KVS(tx * 4 + j, p);
            #pragma unroll
            for (int i = 0; i < 4; ++i)
                #pragma unroll
                for (int j = 0; j < 4; ++j)
                    s[i][j] += a[i] * b[j];
        }

        const bool diag = (kt == qt);
        #pragma unroll
        for (int i = 0; i < 4; ++i)
            #pragma unroll
            for (int j = 0; j < 4; ++j) {
                float sv = s[i][j] * 0.03125f;   // 1/sqrt(D) = 1/32
                if (diag && (tx * 4 + j > ty * 4 + i)) sv = -1e30f;
                s[i][j] = sv;
            }

        // Online softmax: reduce across the 16 tx lanes (within half-warp)
        #pragma unroll
        for (int i = 0; i < 4; ++i) {
            float tm = fmaxf(fmaxf(s[i][0], s[i][1]), fmaxf(s[i][2], s[i][3]));
            #pragma unroll
            for (int off = 1; off < 16; off <<= 1)
                tm = fmaxf(tm, __shfl_xor_sync(0xffffffffu, tm, off));
            float nm   = fmaxf(mreg[i], tm);
            float corr = __expf(mreg[i] - nm);
            mreg[i] = nm;
            float rs = 0.f;
            #pragma unroll
            for (int j = 0; j < 4; ++j) {
                float pv = __expf(s[i][j] - nm);
                Ss[ty * 4 + i][tx * 4 + j] = pv;
                rs += pv;
            }
            #pragma unroll
            for (int off = 1; off < 16; off <<= 1)
                rs += __shfl_xor_sync(0xffffffffu, rs, off);
            lreg[i] = lreg[i] * corr + rs;
            #pragma unroll
            for (int j = 0; j < 4; ++j) o[i][j] *= corr;
        }
        __syncthreads();  // all S-compute KV reads + Ss writes complete

        // Load V tile into KVs (reuse)
        const float* Vb = gV + nbase + (size_t)kt * 64 * DM + h * PP;
        #pragma unroll
        for (int v = 0; v < 4; ++v) {
            int lin = v * 256 + tid;
            int r = lin >> 4;
            int c = (lin & 15) << 2;
            float4 v4 = *(const float4*)(Vb + (size_t)r * DM + c);
            KVS(r, c + 0) = v4.x; KVS(r, c + 1) = v4.y;
            KVS(r, c + 2) = v4.z; KVS(r, c + 3) = v4.w;
        }
        __syncthreads();

        // O += P V
        #pragma unroll 8
        for (int kk = 0; kk < 64; ++kk) {
            float pa[4], vb[4];
            #pragma unroll
            for (int i = 0; i < 4; ++i) pa[i] = Ss[ty * 4 + i][kk];
            #pragma unroll
            for (int j = 0; j < 4; ++j) vb[j] = KVS(kk, tx * 4 + j);
            #pragma unroll
            for (int i = 0; i < 4; ++i)
                #pragma unroll
                for (int j = 0; j < 4; ++j)
                    o[i][j] += pa[i] * vb[j];
        }
    }

    // Epilogue: normalize by l, add residual, write res
    #pragma unroll
    for (int i = 0; i < 4; ++i) {
        float inv = 1.0f / lreg[i];
        size_t grow = (size_t)n * LQL + (size_t)qt * 64 + ty * 4 + i;
        size_t base = grow * DM + h * PP + tx * 4;
        #pragma unroll
        for (int j = 0; j < 4; ++j)
            gRes[base + j] = o[i][j] * inv + query[base + j];
    }
}

// ---------------------------------------------------------------------------
// BatchNorm: deterministic two-stage column stats + fused normalize
// ---------------------------------------------------------------------------
__global__ void __launch_bounds__(256) colstats_partial()
{
    const int col   = blockIdx.x * 256 + threadIdx.x;  // grid.x = 4
    const int chunk = blockIdx.y;                      // 64 chunks x 128 rows
    const float* base = gRes + (size_t)chunk * 128 * DM + col;
    float s = 0.f, q = 0.f;
    #pragma unroll 8
    for (int r = 0; r < 128; ++r) {
        float v = base[(size_t)r * DM];
        s += v;
        q += v * v;
    }
    gPartS[chunk * DM + col] = s;
    gPartQ[chunk * DM + col] = q;
}

__global__ void __launch_bounds__(256) colstats_final(const float* __restrict__ gamma,
                                                      const float* __restrict__ beta)
{
    const int col = blockIdx.x * 256 + threadIdx.x;
    float s = 0.f, q = 0.f;
    #pragma unroll 8
    for (int c = 0; c < 64; ++c) {
        s += gPartS[c * DM + col];
        q += gPartQ[c * DM + col];
    }
    const float invn = 1.0f / (float)MROWS;
    float mean = s * invn;
    float var  = q * invn - mean * mean;
    float inv  = rsqrtf(var + EPSBN);
    float a    = gamma[col] * inv;
    gColA[col] = a;
    gColB[col] = beta[col] - mean * a;
}

__global__ void __launch_bounds__(256) normalize_kernel(float* __restrict__ out)
{
    const size_t idx = (size_t)blockIdx.x * 256 + threadIdx.x;  // float4 index
    float4 v = ((const float4*)gRes)[idx];
    int col = (int)((idx * 4) & (DM - 1));
    float4 r;
    r.x = v.x * gColA[col + 0] + gColB[col + 0];
    r.y = v.y * gColA[col + 1] + gColB[col + 1];
    r.z = v.z * gColA[col + 2] + gColB[col + 2];
    r.w = v.w * gColA[col + 3] + gColB[col + 3];
    ((float4*)out)[idx] = r;
}

// ---------------------------------------------------------------------------
extern "C" void kernel_launch(void* const* d_in, const int* in_sizes, int n_in,
                              void* d_out, int out_size)
{
    const float* query = (const float*)d_in[0];
    const float* key   = (const float*)d_in[1];
    const float* Wq    = (const float*)d_in[2];
    const float* Wk    = (const float*)d_in[3];
    const float* Wv    = (const float*)d_in[4];
    const float* gamma = (const float*)d_in[5];
    const float* beta  = (const float*)d_in[6];
    float* out = (float*)d_out;

    dim3 gg(DM / 64, MROWS / 64);           // (16, 128)
    sgemm_nt<<<gg, 256>>>(query, Wq, 0);
    sgemm_nt<<<gg, 256>>>(key,   Wk, 1);
    sgemm_nt<<<gg, 256>>>(key,   Wv, 2);

    dim3 ga(LQL / 64, HH, NB);              // (32, 16, 4)
    attn_kernel<<<ga, 256>>>(query);

    colstats_partial<<<dim3(DM / 256, 64), 256>>>();
    colstats_final<<<DM / 256, 256>>>(gamma, beta);

    const int total_f4 = MROWS * DM / 4;    // 2,097,152
    normalize_kernel<<<total_f4 / 256, 256>>>(out);
}

// round 3
// speedup vs baseline: 1.8062x; 1.8062x over previous
#include <cuda_runtime.h>
#include <math.h>
#include <stdint.h>

// Problem constants (fixed shapes)
#define NB   4
#define LQL  2048
#define DM   1024
#define HH   16
#define PP   64
#define MROWS (NB*LQL)        // 8192
#define EPSBN 1e-5f

// ---------------- scratch (device globals: allocation-free) ----------------
__device__ float gQ  [MROWS * DM];
__device__ float gK  [MROWS * DM];
__device__ float gV  [MROWS * DM];
__device__ float gRes[MROWS * DM];
__device__ float gPartS[64 * DM];
__device__ float gPartQ[64 * DM];
__device__ float gColA[DM];
__device__ float gColB[DM];

// ============================================================================
// tf32 mma.sync GEMM NT:  C[m][n] = sum_k A[m][k] * W[n][k]
// CTA 128x128, BK=32, 256 threads (8 warps), warp tile 64x32 (m16n8k8 frags).
// cp.async double-buffered; cvt.rna.tf32 applied in-register.
// ============================================================================
#define SM_STRIDE 36                    // floats per smem row (conflict-free)
#define ABUF_F (128 * SM_STRIDE)        // 4608 floats

static __device__ __forceinline__ uint32_t smem_u32(const void* p) {
    uint32_t r;
    asm("{ .reg .u64 t; cvta.to.shared.u64 t, %1; cvt.u32.u64 %0, t; }"
        : "=r"(r) : "l"(p));
    return r;
}
static __device__ __forceinline__ uint32_t f2tf(float x) {
    uint32_t r;
    asm("cvt.rna.tf32.f32 %0, %1;" : "=r"(r) : "f"(x));
    return r;
}
static __device__ __forceinline__ void mma_tf32(float* d, const uint32_t* a,
                                                const uint32_t* b)
{
    asm volatile(
        "mma.sync.aligned.m16n8k8.row.col.f32.tf32.tf32.f32 "
        "{%0,%1,%2,%3}, {%4,%5,%6,%7}, {%8,%9}, {%0,%1,%2,%3};"
        : "+f"(d[0]), "+f"(d[1]), "+f"(d[2]), "+f"(d[3])
        : "r"(a[0]), "r"(a[1]), "r"(a[2]), "r"(a[3]), "r"(b[0]), "r"(b[1]));
}

__global__ void __launch_bounds__(256) gemm_mma(const float* __restrict__ q,
                                                const float* __restrict__ k,
                                                const float* __restrict__ wq,
                                                const float* __restrict__ wk,
                                                const float* __restrict__ wv)
{
    extern __shared__ __align__(16) float sm[];
    const int tid  = threadIdx.x;
    const int lane = tid & 31;
    const int wid  = tid >> 5;
    const int g    = lane >> 2;         // groupID 0..7
    const int tg   = lane & 3;          // threadID_in_group 0..3
    const int wM   = wid >> 2;          // 0..1 -> 64-row slab
    const int wN   = wid & 3;           // 0..3 -> 32-col slab
    const int n0   = blockIdx.x * 128;
    const int m0   = blockIdx.y * 128;
    const int z    = blockIdx.z;

    const float* __restrict__ A = (z == 0) ? q : k;
    const float* __restrict__ W = (z == 0) ? wq : ((z == 1) ? wk : wv);
    float* __restrict__ C = (z == 0) ? gQ : ((z == 1) ? gK : gV);

    float* As[2] = { sm,              sm + ABUF_F };
    float* Bs[2] = { sm + 2 * ABUF_F, sm + 3 * ABUF_F };
    const uint32_t asA[2] = { smem_u32(As[0]), smem_u32(As[1]) };
    const uint32_t asB[2] = { smem_u32(Bs[0]), smem_u32(Bs[1]) };

    float acc[4][4][4] = {};            // [mt][nt][c0..c3]

    const int lr  = tid >> 3;           // load row 0..31 (x4 iters -> 128)
    const int lc4 = tid & 7;            // float4 col 0..7

    // ---- prologue: stage 0 ----
    {
        const int k0 = 0;
        #pragma unroll
        for (int it = 0; it < 4; ++it) {
            int r = lr + it * 32;
            uint32_t da = asA[0] + (uint32_t)(r * SM_STRIDE + lc4 * 4) * 4u;
            const float* sa = A + (size_t)(m0 + r) * DM + k0 + lc4 * 4;
            asm volatile("cp.async.cg.shared.global [%0], [%1], 16;"
                         :: "r"(da), "l"(sa));
            uint32_t db = asB[0] + (uint32_t)(r * SM_STRIDE + lc4 * 4) * 4u;
            const float* sb = W + (size_t)(n0 + r) * DM + k0 + lc4 * 4;
            asm volatile("cp.async.cg.shared.global [%0], [%1], 16;"
                         :: "r"(db), "l"(sb));
        }
        asm volatile("cp.async.commit_group;" ::: "memory");
    }

    const int NSTAGE = DM / 32;         // 32
    for (int s = 0; s < NSTAGE; ++s) {
        const int buf = s & 1;
        if (s + 1 < NSTAGE) {
            const int nb = buf ^ 1;
            const int k0 = (s + 1) * 32;
            #pragma unroll
            for (int it = 0; it < 4; ++it) {
                int r = lr + it * 32;
                uint32_t da = asA[nb] + (uint32_t)(r * SM_STRIDE + lc4 * 4) * 4u;
                const float* sa = A + (size_t)(m0 + r) * DM + k0 + lc4 * 4;
                asm volatile("cp.async.cg.shared.global [%0], [%1], 16;"
                             :: "r"(da), "l"(sa));
                uint32_t db = asB[nb] + (uint32_t)(r * SM_STRIDE + lc4 * 4) * 4u;
                const float* sb = W + (size_t)(n0 + r) * DM + k0 + lc4 * 4;
                asm volatile("cp.async.cg.shared.global [%0], [%1], 16;"
                             :: "r"(db), "l"(sb));
            }
            asm volatile("cp.async.commit_group;" ::: "memory");
            asm volatile("cp.async.wait_group %0;" :: "n"(1) : "memory");
        } else {
            asm volatile("cp.async.wait_group %0;" :: "n"(0) : "memory");
        }
        __syncthreads();

        const float* pa = As[buf];
        const float* pb = Bs[buf];
        #pragma unroll
        for (int kk = 0; kk < 4; ++kk) {
            const int kb = kk * 8;
            uint32_t af[4][4];
            #pragma unroll
            for (int mt = 0; mt < 4; ++mt) {
                int row = wM * 64 + mt * 16 + g;
                const float* base = pa + row * SM_STRIDE + kb + tg;
                af[mt][0] = f2tf(base[0]);
                af[mt][1] = f2tf(base[8 * SM_STRIDE]);
                af[mt][2] = f2tf(base[4]);
                af[mt][3] = f2tf(base[8 * SM_STRIDE + 4]);
            }
            uint32_t bf[4][2];
            #pragma unroll
            for (int nt = 0; nt < 4; ++nt) {
                int n = wN * 32 + nt * 8 + g;
                const float* base = pb + n * SM_STRIDE + kb + tg;
                bf[nt][0] = f2tf(base[0]);
                bf[nt][1] = f2tf(base[4]);
            }
            #pragma unroll
            for (int mt = 0; mt < 4; ++mt)
                #pragma unroll
                for (int nt = 0; nt < 4; ++nt)
                    mma_tf32(acc[mt][nt], af[mt], bf[nt]);
        }
        __syncthreads();
    }

    // ---- epilogue ----
    #pragma unroll
    for (int mt = 0; mt < 4; ++mt) {
        int row = m0 + wM * 64 + mt * 16 + g;
        #pragma unroll
        for (int nt = 0; nt < 4; ++nt) {
            int col = n0 + wN * 32 + nt * 8 + tg * 2;
            float2 v0 = make_float2(acc[mt][nt][0], acc[mt][nt][1]);
            float2 v1 = make_float2(acc[mt][nt][2], acc[mt][nt][3]);
            *(float2*)(C + (size_t)row * DM + col) = v0;
            *(float2*)(C + (size_t)(row + 8) * DM + col) = v1;
        }
    }
}

// ---------------------------------------------------------------------------
// Causal flash attention (SIMT fp32), one (n, h, 64-row q-tile) per block.
// ---------------------------------------------------------------------------
#define KVS(r, c) KVs[((r) << 6) + (((c) + (r)) & 63)]

__global__ void __launch_bounds__(256) attn_kernel(const float* __restrict__ query)
{
    __shared__ float Qs[64][64];
    __shared__ float KVs[64 * 64];
    __shared__ float Ss[64][64];

    const int tid = threadIdx.x;
    const int tx  = tid & 15;
    const int ty  = tid >> 4;
    const int qt  = blockIdx.x;
    const int h   = blockIdx.y;
    const int n   = blockIdx.z;

    const size_t nbase = (size_t)n * LQL * DM;
    const float* Qb = gQ + nbase + (size_t)qt * 64 * DM + h * PP;

    #pragma unroll
    for (int v = 0; v < 4; ++v) {
        int lin = v * 256 + tid;
        int r = lin >> 4;
        int c = (lin & 15) << 2;
        float4 q4 = *(const float4*)(Qb + (size_t)r * DM + c);
        Qs[r][c + 0] = q4.x; Qs[r][c + 1] = q4.y;
        Qs[r][c + 2] = q4.z; Qs[r][c + 3] = q4.w;
    }

    float o[4][4] = {};
    float mreg[4], lreg[4];
    #pragma unroll
    for (int i = 0; i < 4; ++i) { mreg[i] = -INFINITY; lreg[i] = 0.f; }

    for (int kt = 0; kt <= qt; ++kt) {
        __syncthreads();

        const float* Kb = gK + nbase + (size_t)kt * 64 * DM + h * PP;
        #pragma unroll
        for (int v = 0; v < 4; ++v) {
            int lin = v * 256 + tid;
            int r = lin >> 4;
            int c = (lin & 15) << 2;
            float4 k4 = *(const float4*)(Kb + (size_t)r * DM + c);
            KVS(r, c + 0) = k4.x; KVS(r, c + 1) = k4.y;
            KVS(r, c + 2) = k4.z; KVS(r, c + 3) = k4.w;
        }
        __syncthreads();

        float s[4][4] = {};
        #pragma unroll 8
        for (int p = 0; p < 64; ++p) {
            float a[4], b[4];
            #pragma unroll
            for (int i = 0; i < 4; ++i) a[i] = Qs[ty * 4 + i][p];
            #pragma unroll
            for (int j = 0; j < 4; ++j) b[j] = KVS(tx * 4 + j, p);
            #pragma unroll
            for (int i = 0; i < 4; ++i)
                #pragma unroll
                for (int j = 0; j < 4; ++j)
                    s[i][j] += a[i] * b[j];
        }

        const bool diag = (kt == qt);
        #pragma unroll
        for (int i = 0; i < 4; ++i)
            #pragma unroll
            for (int j = 0; j < 4; ++j) {
                float sv = s[i][j] * 0.03125f;
                if (diag && (tx * 4 + j > ty * 4 + i)) sv = -1e30f;
                s[i][j] = sv;
            }

        #pragma unroll
        for (int i = 0; i < 4; ++i) {
            float tm = fmaxf(fmaxf(s[i][0], s[i][1]), fmaxf(s[i][2], s[i][3]));
            #pragma unroll
            for (int off = 1; off < 16; off <<= 1)
                tm = fmaxf(tm, __shfl_xor_sync(0xffffffffu, tm, off));
            float nm   = fmaxf(mreg[i], tm);
            float corr = __expf(mreg[i] - nm);
            mreg[i] = nm;
            float rs = 0.f;
            #pragma unroll
            for (int j = 0; j < 4; ++j) {
                float pv = __expf(s[i][j] - nm);
                Ss[ty * 4 + i][tx * 4 + j] = pv;
                rs += pv;
            }
            #pragma unroll
            for (int off = 1; off < 16; off <<= 1)
                rs += __shfl_xor_sync(0xffffffffu, rs, off);
            lreg[i] = lreg[i] * corr + rs;
            #pragma unroll
            for (int j = 0; j < 4; ++j) o[i][j] *= corr;
        }
        __syncthreads();

        const float* Vb = gV + nbase + (size_t)kt * 64 * DM + h * PP;
        #pragma unroll
        for (int v = 0; v < 4; ++v) {
            int lin = v * 256 + tid;
            int r = lin >> 4;
            int c = (lin & 15) << 2;
            float4 v4 = *(const float4*)(Vb + (size_t)r * DM + c);
            KVS(r, c + 0) = v4.x; KVS(r, c + 1) = v4.y;
            KVS(r, c + 2) = v4.z; KVS(r, c + 3) = v4.w;
        }
        __syncthreads();

        #pragma unroll 8
        for (int kk = 0; kk < 64; ++kk) {
            float pa[4], vb[4];
            #pragma unroll
            for (int i = 0; i < 4; ++i) pa[i] = Ss[ty * 4 + i][kk];
            #pragma unroll
            for (int j = 0; j < 4; ++j) vb[j] = KVS(kk, tx * 4 + j);
            #pragma unroll
            for (int i = 0; i < 4; ++i)
                #pragma unroll
                for (int j = 0; j < 4; ++j)
                    o[i][j] += pa[i] * vb[j];
        }
    }

    #pragma unroll
    for (int i = 0; i < 4; ++i) {
        float inv = 1.0f / lreg[i];
        size_t grow = (size_t)n * LQL + (size_t)qt * 64 + ty * 4 + i;
        size_t base = grow * DM + h * PP + tx * 4;
        #pragma unroll
        for (int j = 0; j < 4; ++j)
            gRes[base + j] = o[i][j] * inv + query[base + j];
    }
}

// ---------------------------------------------------------------------------
// BatchNorm: deterministic two-stage column stats + fused normalize
// ---------------------------------------------------------------------------
__global__ void __launch_bounds__(256) colstats_partial()
{
    const int col   = blockIdx.x * 256 + threadIdx.x;
    const int chunk = blockIdx.y;
    const float* base = gRes + (size_t)chunk * 128 * DM + col;
    float s = 0.f, q = 0.f;
    #pragma unroll 8
    for (int r = 0; r < 128; ++r) {
        float v = base[(size_t)r * DM];
        s += v;
        q += v * v;
    }
    gPartS[chunk * DM + col] = s;
    gPartQ[chunk * DM + col] = q;
}

__global__ void __launch_bounds__(256) colstats_final(const float* __restrict__ gamma,
                                                      const float* __restrict__ beta)
{
    const int col = blockIdx.x * 256 + threadIdx.x;
    float s = 0.f, q = 0.f;
    #pragma unroll 8
    for (int c = 0; c < 64; ++c) {
        s += gPartS[c * DM + col];
        q += gPartQ[c * DM + col];
    }
    const float invn = 1.0f / (float)MROWS;
    float mean = s * invn;
    float var  = q * invn - mean * mean;
    float inv  = rsqrtf(var + EPSBN);
    float a    = gamma[col] * inv;
    gColA[col] = a;
    gColB[col] = beta[col] - mean * a;
}

__global__ void __launch_bounds__(256) normalize_kernel(float* __restrict__ out)
{
    const size_t idx = (size_t)blockIdx.x * 256 + threadIdx.x;
    float4 v = ((const float4*)gRes)[idx];
    int col = (int)((idx * 4) & (DM - 1));
    float4 r;
    r.x = v.x * gColA[col + 0] + gColB[col + 0];
    r.y = v.y * gColA[col + 1] + gColB[col + 1];
    r.z = v.z * gColA[col + 2] + gColB[col + 2];
    r.w = v.w * gColA[col + 3] + gColB[col + 3];
    ((float4*)out)[idx] = r;
}

// ---------------------------------------------------------------------------
extern "C" void kernel_launch(void* const* d_in, const int* in_sizes, int n_in,
                              void* d_out, int out_size)
{
    const float* query = (const float*)d_in[0];
    const float* key   = (const float*)d_in[1];
    const float* Wq    = (const float*)d_in[2];
    const float* Wk    = (const float*)d_in[3];
    const float* Wv    = (const float*)d_in[4];
    const float* gamma = (const float*)d_in[5];
    const float* beta  = (const float*)d_in[6];
    float* out = (float*)d_out;

    // tf32 mma.sync projections: z=0 Q, z=1 K, z=2 V
    const int smem_bytes = 4 * ABUF_F * 4;   // 73728
    cudaFuncSetAttribute(gemm_mma, cudaFuncAttributeMaxDynamicSharedMemorySize,
                         smem_bytes);
    dim3 gg(DM / 128, MROWS / 128, 3);       // (8, 64, 3)
    gemm_mma<<<gg, 256, smem_bytes>>>(query, key, Wq, Wk, Wv);

    dim3 ga(LQL / 64, HH, NB);               // (32, 16, 4)
    attn_kernel<<<ga, 256>>>(query);

    colstats_partial<<<dim3(DM / 256, 64), 256>>>();
    colstats_final<<<DM / 256, 256>>>(gamma, beta);

    const int total_f4 = MROWS * DM / 4;
    normalize_kernel<<<total_f4 / 256, 256>>>(out);
}

// round 4
// speedup vs baseline: 3.9919x; 2.2101x over previous
#include <cuda_runtime.h>
#include <math.h>
#include <stdint.h>

// Problem constants (fixed shapes)
#define NB   4
#define LQL  2048
#define DM   1024
#define HH   16
#define PP   64
#define MROWS (NB*LQL)        // 8192
#define EPSBN 1e-5f

// ---------------- scratch (device globals: allocation-free) ----------------
__device__ float gQ  [MROWS * DM];
__device__ float gK  [MROWS * DM];
__device__ float gV  [MROWS * DM];
__device__ float gRes[MROWS * DM];
__device__ float gPartS[64 * DM];
__device__ float gPartQ[64 * DM];
__device__ float gColA[DM];
__device__ float gColB[DM];

// ---------------- shared helpers ----------------
static __device__ __forceinline__ uint32_t smem_u32(const void* p) {
    uint32_t r;
    asm("{ .reg .u64 t; cvta.to.shared.u64 t, %1; cvt.u32.u64 %0, t; }"
        : "=r"(r) : "l"(p));
    return r;
}
static __device__ __forceinline__ uint32_t f2tf(float x) {
    uint32_t r;
    asm("cvt.rna.tf32.f32 %0, %1;" : "=r"(r) : "f"(x));
    return r;
}
static __device__ __forceinline__ void mma_tf32(float* d, const uint32_t* a,
                                                const uint32_t* b)
{
    asm volatile(
        "mma.sync.aligned.m16n8k8.row.col.f32.tf32.tf32.f32 "
        "{%0,%1,%2,%3}, {%4,%5,%6,%7}, {%8,%9}, {%0,%1,%2,%3};"
        : "+f"(d[0]), "+f"(d[1]), "+f"(d[2]), "+f"(d[3])
        : "r"(a[0]), "r"(a[1]), "r"(a[2]), "r"(a[3]), "r"(b[0]), "r"(b[1]));
}

// ============================================================================
// tf32 mma.sync GEMM NT:  C[m][n] = sum_k A[m][k] * W[n][k]
// CTA 128x128, BK=32, 256 threads (8 warps), warp tile 64x32.
// ============================================================================
#define SM_STRIDE 36
#define ABUF_F (128 * SM_STRIDE)

__global__ void __launch_bounds__(256) gemm_mma(const float* __restrict__ q,
                                                const float* __restrict__ k,
                                                const float* __restrict__ wq,
                                                const float* __restrict__ wk,
                                                const float* __restrict__ wv)
{
    extern __shared__ __align__(16) float sm[];
    const int tid  = threadIdx.x;
    const int lane = tid & 31;
    const int wid  = tid >> 5;
    const int g    = lane >> 2;
    const int tg   = lane & 3;
    const int wM   = wid >> 2;
    const int wN   = wid & 3;
    const int n0   = blockIdx.x * 128;
    const int m0   = blockIdx.y * 128;
    const int z    = blockIdx.z;

    const float* __restrict__ A = (z == 0) ? q : k;
    const float* __restrict__ W = (z == 0) ? wq : ((z == 1) ? wk : wv);
    float* __restrict__ C = (z == 0) ? gQ : ((z == 1) ? gK : gV);

    float* As[2] = { sm,              sm + ABUF_F };
    float* Bs[2] = { sm + 2 * ABUF_F, sm + 3 * ABUF_F };
    const uint32_t asA[2] = { smem_u32(As[0]), smem_u32(As[1]) };
    const uint32_t asB[2] = { smem_u32(Bs[0]), smem_u32(Bs[1]) };

    float acc[4][4][4] = {};

    const int lr  = tid >> 3;
    const int lc4 = tid & 7;

    {
        #pragma unroll
        for (int it = 0; it < 4; ++it) {
            int r = lr + it * 32;
            uint32_t da = asA[0] + (uint32_t)(r * SM_STRIDE + lc4 * 4) * 4u;
            const float* sa = A + (size_t)(m0 + r) * DM + lc4 * 4;
            asm volatile("cp.async.cg.shared.global [%0], [%1], 16;"
                         :: "r"(da), "l"(sa));
            uint32_t db = asB[0] + (uint32_t)(r * SM_STRIDE + lc4 * 4) * 4u;
            const float* sb = W + (size_t)(n0 + r) * DM + lc4 * 4;
            asm volatile("cp.async.cg.shared.global [%0], [%1], 16;"
                         :: "r"(db), "l"(sb));
        }
        asm volatile("cp.async.commit_group;" ::: "memory");
    }

    const int NSTAGE = DM / 32;
    for (int s = 0; s < NSTAGE; ++s) {
        const int buf = s & 1;
        if (s + 1 < NSTAGE) {
            const int nb = buf ^ 1;
            const int k0 = (s + 1) * 32;
            #pragma unroll
            for (int it = 0; it < 4; ++it) {
                int r = lr + it * 32;
                uint32_t da = asA[nb] + (uint32_t)(r * SM_STRIDE + lc4 * 4) * 4u;
                const float* sa = A + (size_t)(m0 + r) * DM + k0 + lc4 * 4;
                asm volatile("cp.async.cg.shared.global [%0], [%1], 16;"
                             :: "r"(da), "l"(sa));
                uint32_t db = asB[nb] + (uint32_t)(r * SM_STRIDE + lc4 * 4) * 4u;
                const float* sb = W + (size_t)(n0 + r) * DM + k0 + lc4 * 4;
                asm volatile("cp.async.cg.shared.global [%0], [%1], 16;"
                             :: "r"(db), "l"(sb));
            }
            asm volatile("cp.async.commit_group;" ::: "memory");
            asm volatile("cp.async.wait_group %0;" :: "n"(1) : "memory");
        } else {
            asm volatile("cp.async.wait_group %0;" :: "n"(0) : "memory");
        }
        __syncthreads();

        const float* pa = As[buf];
        const float* pb = Bs[buf];
        #pragma unroll
        for (int kk = 0; kk < 4; ++kk) {
            const int kb = kk * 8;
            uint32_t af[4][4];
            #pragma unroll
            for (int mt = 0; mt < 4; ++mt) {
                int row = wM * 64 + mt * 16 + g;
                const float* base = pa + row * SM_STRIDE + kb + tg;
                af[mt][0] = f2tf(base[0]);
                af[mt][1] = f2tf(base[8 * SM_STRIDE]);
                af[mt][2] = f2tf(base[4]);
                af[mt][3] = f2tf(base[8 * SM_STRIDE + 4]);
            }
            uint32_t bf[4][2];
            #pragma unroll
            for (int nt = 0; nt < 4; ++nt) {
                int nn = wN * 32 + nt * 8 + g;
                const float* base = pb + nn * SM_STRIDE + kb + tg;
                bf[nt][0] = f2tf(base[0]);
                bf[nt][1] = f2tf(base[4]);
            }
            #pragma unroll
            for (int mt = 0; mt < 4; ++mt)
                #pragma unroll
                for (int nt = 0; nt < 4; ++nt)
                    mma_tf32(acc[mt][nt], af[mt], bf[nt]);
        }
        __syncthreads();
    }

    #pragma unroll
    for (int mt = 0; mt < 4; ++mt) {
        int row = m0 + wM * 64 + mt * 16 + g;
        #pragma unroll
        for (int nt = 0; nt < 4; ++nt) {
            int col = n0 + wN * 32 + nt * 8 + tg * 2;
            float2 v0 = make_float2(acc[mt][nt][0], acc[mt][nt][1]);
            float2 v1 = make_float2(acc[mt][nt][2], acc[mt][nt][3]);
            *(float2*)(C + (size_t)row * DM + col) = v0;
            *(float2*)(C + (size_t)(row + 8) * DM + col) = v1;
        }
    }
}

// ============================================================================
// tf32 mma.sync causal flash attention.
// Q-tile 128 x 64, 4 warps (32 rows each), K/V tiles 64 x 64 double-buffered.
// Smem: K0,V0,K1,V1 (4 x 16KB) + Ss (32KB) = 96KB. XOR-swizzled layout.
// ============================================================================
#define SW(r, c) (((r) << 6) + ((c) ^ (((r) & 7) << 3)))

__global__ void __launch_bounds__(128) attn_mma(const float* __restrict__ query)
{
    extern __shared__ __align__(16) float sm[];
    float* Kb[2] = { sm,           sm + 8192 };
    float* Vb[2] = { sm + 4096,    sm + 12288 };
    float* Ss    = sm + 16384;
    const uint32_t sK[2] = { smem_u32(Kb[0]), smem_u32(Kb[1]) };
    const uint32_t sV[2] = { smem_u32(Vb[0]), smem_u32(Vb[1]) };

    const int tid  = threadIdx.x;
    const int lane = tid & 31;
    const int wid  = tid >> 5;
    const int g    = lane >> 2;
    const int tg   = lane & 3;
    const int qt   = blockIdx.x;   // 0..15 (128-row q tiles)
    const int h    = blockIdx.y;
    const int n    = blockIdx.z;

    const size_t nbase = (size_t)n * LQL * DM;
    const int hcol = h * PP;
    const int KT = 2 * qt + 2;     // number of 64-row K tiles

    // ---- prefetch K/V tile 0 ----
    {
        const float* Kg = gK + nbase + hcol;
        const float* Vg = gV + nbase + hcol;
        #pragma unroll
        for (int i = 0; i < 8; ++i) {
            int idx = tid + i * 128;
            int r = idx >> 4, c = (idx & 15) << 2;
            uint32_t dst = (uint32_t)SW(r, c) * 4u;
            asm volatile("cp.async.cg.shared.global [%0], [%1], 16;"
                         :: "r"(sK[0] + dst), "l"(Kg + (size_t)r * DM + c));
            asm volatile("cp.async.cg.shared.global [%0], [%1], 16;"
                         :: "r"(sV[0] + dst), "l"(Vg + (size_t)r * DM + c));
        }
        asm volatile("cp.async.commit_group;" ::: "memory");
    }

    // ---- stage Q tile into Ss, then load register fragments ----
    {
        const float* Qg = gQ + nbase + (size_t)qt * 128 * DM + hcol;
        #pragma unroll
        for (int i = 0; i < 16; ++i) {
            int idx = tid + i * 128;
            int r = idx >> 4, c = (idx & 15) << 2;
            float4 v = *(const float4*)(Qg + (size_t)r * DM + c);
            *(float4*)(Ss + SW(r, c)) = v;
        }
    }
    __syncthreads();
    uint32_t qf[2][8][4];
    #pragma unroll
    for (int mb = 0; mb < 2; ++mb) {
        int r0 = wid * 32 + mb * 16 + g;
        #pragma unroll
        for (int ks = 0; ks < 8; ++ks) {
            qf[mb][ks][0] = f2tf(Ss[SW(r0,     ks * 8 + tg)]);
            qf[mb][ks][1] = f2tf(Ss[SW(r0 + 8, ks * 8 + tg)]);
            qf[mb][ks][2] = f2tf(Ss[SW(r0,     ks * 8 + tg + 4)]);
            qf[mb][ks][3] = f2tf(Ss[SW(r0 + 8, ks * 8 + tg + 4)]);
        }
    }
    __syncthreads();

    float o[2][8][4] = {};
    float mrow[2][2], lrow[2][2];
    #pragma unroll
    for (int a = 0; a < 2; ++a)
        #pragma unroll
        for (int b = 0; b < 2; ++b) { mrow[a][b] = -INFINITY; lrow[a][b] = 0.f; }

    for (int kt = 0; kt < KT; ++kt) {
        const int buf = kt & 1;
        // prefetch next tile into other buffer
        if (kt + 1 < KT) {
            const float* Kg = gK + nbase + (size_t)(kt + 1) * 64 * DM + hcol;
            const float* Vg = gV + nbase + (size_t)(kt + 1) * 64 * DM + hcol;
            #pragma unroll
            for (int i = 0; i < 8; ++i) {
                int idx = tid + i * 128;
                int r = idx >> 4, c = (idx & 15) << 2;
                uint32_t dst = (uint32_t)SW(r, c) * 4u;
                asm volatile("cp.async.cg.shared.global [%0], [%1], 16;"
                             :: "r"(sK[buf ^ 1] + dst), "l"(Kg + (size_t)r * DM + c));
                asm volatile("cp.async.cg.shared.global [%0], [%1], 16;"
                             :: "r"(sV[buf ^ 1] + dst), "l"(Vg + (size_t)r * DM + c));
            }
            asm volatile("cp.async.commit_group;" ::: "memory");
            asm volatile("cp.async.wait_group %0;" :: "n"(1) : "memory");
        } else {
            asm volatile("cp.async.wait_group %0;" :: "n"(0) : "memory");
        }
        __syncthreads();

        const float* Ks = Kb[buf];
        const float* Vs = Vb[buf];

        // ---- S = Q K^T ----
        float s[2][8][4] = {};
        #pragma unroll
        for (int ks = 0; ks < 8; ++ks) {
            #pragma unroll
            for (int nb = 0; nb < 8; ++nb) {
                uint32_t bb[2];
                bb[0] = f2tf(Ks[SW(nb * 8 + g, ks * 8 + tg)]);
                bb[1] = f2tf(Ks[SW(nb * 8 + g, ks * 8 + tg + 4)]);
                mma_tf32(s[0][nb], qf[0][ks], bb);
                mma_tf32(s[1][nb], qf[1][ks], bb);
            }
        }

        // ---- mask + online softmax ----
        const bool tail = (kt >= 2 * qt);
        #pragma unroll
        for (int mb = 0; mb < 2; ++mb) {
            #pragma unroll
            for (int rr = 0; rr < 2; ++rr) {
                const int grow = qt * 128 + wid * 32 + mb * 16 + rr * 8 + g;
                float tm = -INFINITY;
                #pragma unroll
                for (int nb = 0; nb < 8; ++nb) {
                    float v0 = s[mb][nb][rr * 2 + 0] * 0.03125f;
                    float v1 = s[mb][nb][rr * 2 + 1] * 0.03125f;
                    if (tail) {
                        int c0 = kt * 64 + nb * 8 + tg * 2;
                        if (c0     > grow) v0 = -1e30f;
                        if (c0 + 1 > grow) v1 = -1e30f;
                    }
                    s[mb][nb][rr * 2 + 0] = v0;
                    s[mb][nb][rr * 2 + 1] = v1;
                    tm = fmaxf(tm, fmaxf(v0, v1));
                }
                tm = fmaxf(tm, __shfl_xor_sync(0xffffffffu, tm, 1));
                tm = fmaxf(tm, __shfl_xor_sync(0xffffffffu, tm, 2));
                float nm   = fmaxf(mrow[mb][rr], tm);
                float corr = __expf(mrow[mb][rr] - nm);
                mrow[mb][rr] = nm;
                float rs = 0.f;
                #pragma unroll
                for (int nb = 0; nb < 8; ++nb) {
                    float p0 = __expf(s[mb][nb][rr * 2 + 0] - nm);
                    float p1 = __expf(s[mb][nb][rr * 2 + 1] - nm);
                    s[mb][nb][rr * 2 + 0] = p0;
                    s[mb][nb][rr * 2 + 1] = p1;
                    rs += p0 + p1;
                }
                rs += __shfl_xor_sync(0xffffffffu, rs, 1);
                rs += __shfl_xor_sync(0xffffffffu, rs, 2);
                lrow[mb][rr] = lrow[mb][rr] * corr + rs;
                #pragma unroll
                for (int nb = 0; nb < 8; ++nb) {
                    o[mb][nb][rr * 2 + 0] *= corr;
                    o[mb][nb][rr * 2 + 1] *= corr;
                }
            }
        }

        // ---- store P to Ss ----
        #pragma unroll
        for (int mb = 0; mb < 2; ++mb) {
            int r0 = wid * 32 + mb * 16 + g;
            #pragma unroll
            for (int nb = 0; nb < 8; ++nb) {
                *(float2*)(Ss + SW(r0,     nb * 8 + tg * 2)) =
                    make_float2(s[mb][nb][0], s[mb][nb][1]);
                *(float2*)(Ss + SW(r0 + 8, nb * 8 + tg * 2)) =
                    make_float2(s[mb][nb][2], s[mb][nb][3]);
            }
        }
        __syncthreads();

        // ---- O += P V ----
        #pragma unroll
        for (int ks = 0; ks < 8; ++ks) {
            uint32_t af[2][4];
            #pragma unroll
            for (int mb = 0; mb < 2; ++mb) {
                int r0 = wid * 32 + mb * 16 + g;
                af[mb][0] = f2tf(Ss[SW(r0,     ks * 8 + tg)]);
                af[mb][1] = f2tf(Ss[SW(r0 + 8, ks * 8 + tg)]);
                af[mb][2] = f2tf(Ss[SW(r0,     ks * 8 + tg + 4)]);
                af[mb][3] = f2tf(Ss[SW(r0 + 8, ks * 8 + tg + 4)]);
            }
            #pragma unroll
            for (int nb = 0; nb < 8; ++nb) {
                uint32_t bb[2];
                bb[0] = f2tf(Vs[SW(ks * 8 + tg,     nb * 8 + g)]);
                bb[1] = f2tf(Vs[SW(ks * 8 + tg + 4, nb * 8 + g)]);
                mma_tf32(o[0][nb], af[0], bb);
                mma_tf32(o[1][nb], af[1], bb);
            }
        }
        __syncthreads();
    }

    // ---- epilogue: normalize, add residual, write gRes ----
    #pragma unroll
    for (int mb = 0; mb < 2; ++mb) {
        #pragma unroll
        for (int rr = 0; rr < 2; ++rr) {
            float inv = 1.0f / lrow[mb][rr];
            int grow = qt * 128 + wid * 32 + mb * 16 + rr * 8 + g;
            size_t rowoff = nbase + (size_t)grow * DM + hcol;
            #pragma unroll
            for (int nb = 0; nb < 8; ++nb) {
                int c = nb * 8 + tg * 2;
                float2 qv = *(const float2*)(query + rowoff + c);
                float2 w;
                w.x = o[mb][nb][rr * 2 + 0] * inv + qv.x;
                w.y = o[mb][nb][rr * 2 + 1] * inv + qv.y;
                *(float2*)(gRes + rowoff + c) = w;
            }
        }
    }
}

// ---------------------------------------------------------------------------
// BatchNorm: deterministic two-stage column stats + fused normalize
// ---------------------------------------------------------------------------
__global__ void __launch_bounds__(256) colstats_partial()
{
    const int col   = blockIdx.x * 256 + threadIdx.x;
    const int chunk = blockIdx.y;
    const float* base = gRes + (size_t)chunk * 128 * DM + col;
    float s = 0.f, q = 0.f;
    #pragma unroll 8
    for (int r = 0; r < 128; ++r) {
        float v = base[(size_t)r * DM];
        s += v;
        q += v * v;
    }
    gPartS[chunk * DM + col] = s;
    gPartQ[chunk * DM + col] = q;
}

__global__ void __launch_bounds__(256) colstats_final(const float* __restrict__ gamma,
                                                      const float* __restrict__ beta)
{
    const int col = blockIdx.x * 256 + threadIdx.x;
    float s = 0.f, q = 0.f;
    #pragma unroll 8
    for (int c = 0; c < 64; ++c) {
        s += gPartS[c * DM + col];
        q += gPartQ[c * DM + col];
    }
    const float invn = 1.0f / (float)MROWS;
    float mean = s * invn;
    float var  = q * invn - mean * mean;
    float inv  = rsqrtf(var + EPSBN);
    float a    = gamma[col] * inv;
    gColA[col] = a;
    gColB[col] = beta[col] - mean * a;
}

__global__ void __launch_bounds__(256) normalize_kernel(float* __restrict__ out)
{
    const size_t idx = (size_t)blockIdx.x * 256 + threadIdx.x;
    float4 v = ((const float4*)gRes)[idx];
    int col = (int)((idx * 4) & (DM - 1));
    float4 r;
    r.x = v.x * gColA[col + 0] + gColB[col + 0];
    r.y = v.y * gColA[col + 1] + gColB[col + 1];
    r.z = v.z * gColA[col + 2] + gColB[col + 2];
    r.w = v.w * gColA[col + 3] + gColB[col + 3];
    ((float4*)out)[idx] = r;
}

// ---------------------------------------------------------------------------
extern "C" void kernel_launch(void* const* d_in, const int* in_sizes, int n_in,
                              void* d_out, int out_size)
{
    const float* query = (const float*)d_in[0];
    const float* key   = (const float*)d_in[1];
    const float* Wq    = (const float*)d_in[2];
    const float* Wk    = (const float*)d_in[3];
    const float* Wv    = (const float*)d_in[4];
    const float* gamma = (const float*)d_in[5];
    const float* beta  = (const float*)d_in[6];
    float* out = (float*)d_out;

    // tf32 mma.sync projections: z=0 Q, z=1 K, z=2 V
    const int gemm_smem = 4 * ABUF_F * 4;    // 73728
    cudaFuncSetAttribute(gemm_mma, cudaFuncAttributeMaxDynamicSharedMemorySize,
                         gemm_smem);
    dim3 gg(DM / 128, MROWS / 128, 3);       // (8, 64, 3)
    gemm_mma<<<gg, 256, gemm_smem>>>(query, key, Wq, Wk, Wv);

    // tf32 mma.sync flash attention
    const int attn_smem = 24576 * 4;         // 96KB
    cudaFuncSetAttribute(attn_mma, cudaFuncAttributeMaxDynamicSharedMemorySize,
                         attn_smem);
    dim3 ga(LQL / 128, HH, NB);              // (16, 16, 4)
    attn_mma<<<ga, 128, attn_smem>>>(query);

    colstats_partial<<<dim3(DM / 256, 64), 256>>>();
    colstats_final<<<DM / 256, 256>>>(gamma, beta);

    const int total_f4 = MROWS * DM / 4;
    normalize_kernel<<<total_f4 / 256, 256>>>(out);
}

// round 5
// speedup vs baseline: 4.4226x; 1.1079x over previous
#include <cuda_runtime.h>
#include <math.h>
#include <stdint.h>

// Problem constants (fixed shapes)
#define NB   4
#define LQL  2048
#define DM   1024
#define HH   16
#define PP   64
#define MROWS (NB*LQL)        // 8192
#define EPSBN 1e-5f

// ---------------- scratch (device globals: allocation-free) ----------------
__device__ float gQ  [MROWS * DM];   // tf32-rounded Q projection
__device__ float gK  [MROWS * DM];   // tf32-rounded K projection
__device__ float gV  [MROWS * DM];   // tf32-rounded V projection
__device__ float gRes[MROWS * DM];
__device__ float gPartS[64 * DM];
__device__ float gPartQ[64 * DM];
__device__ float gColA[DM];
__device__ float gColB[DM];

// ---------------- shared helpers ----------------
static __device__ __forceinline__ uint32_t smem_u32(const void* p) {
    uint32_t r;
    asm("{ .reg .u64 t; cvta.to.shared.u64 t, %1; cvt.u32.u64 %0, t; }"
        : "=r"(r) : "l"(p));
    return r;
}
static __device__ __forceinline__ uint32_t f2tf(float x) {
    uint32_t r;
    asm("cvt.rna.tf32.f32 %0, %1;" : "=r"(r) : "f"(x));
    return r;
}
static __device__ __forceinline__ void mma_tf32(float* d, const uint32_t* a,
                                                const uint32_t* b)
{
    asm volatile(
        "mma.sync.aligned.m16n8k8.row.col.f32.tf32.tf32.f32 "
        "{%0,%1,%2,%3}, {%4,%5,%6,%7}, {%8,%9}, {%0,%1,%2,%3};"
        : "+f"(d[0]), "+f"(d[1]), "+f"(d[2]), "+f"(d[3])
        : "r"(a[0]), "r"(a[1]), "r"(a[2]), "r"(a[3]), "r"(b[0]), "r"(b[1]));
}
static __device__ __forceinline__ uint32_t ld_u32(const float* p) {
    return __float_as_uint(*p);
}

// ============================================================================
// tf32 mma.sync GEMM NT:  C[m][n] = round_tf32( sum_k A[m][k] * W[n][k] )
// CTA 128x128, BK=32, 256 threads (8 warps), warp tile 64x32.
// Epilogue stores tf32-ROUNDED results so downstream attention skips all cvt.
// ============================================================================
#define SM_STRIDE 36
#define ABUF_F (128 * SM_STRIDE)

__global__ void __launch_bounds__(256) gemm_mma(const float* __restrict__ q,
                                                const float* __restrict__ k,
                                                const float* __restrict__ wq,
                                                const float* __restrict__ wk,
                                                const float* __restrict__ wv)
{
    extern __shared__ __align__(16) float sm[];
    const int tid  = threadIdx.x;
    const int lane = tid & 31;
    const int wid  = tid >> 5;
    const int g    = lane >> 2;
    const int tg   = lane & 3;
    const int wM   = wid >> 2;
    const int wN   = wid & 3;
    const int n0   = blockIdx.x * 128;
    const int m0   = blockIdx.y * 128;
    const int z    = blockIdx.z;

    const float* __restrict__ A = (z == 0) ? q : k;
    const float* __restrict__ W = (z == 0) ? wq : ((z == 1) ? wk : wv);
    float* __restrict__ C = (z == 0) ? gQ : ((z == 1) ? gK : gV);

    float* As[2] = { sm,              sm + ABUF_F };
    float* Bs[2] = { sm + 2 * ABUF_F, sm + 3 * ABUF_F };
    const uint32_t asA[2] = { smem_u32(As[0]), smem_u32(As[1]) };
    const uint32_t asB[2] = { smem_u32(Bs[0]), smem_u32(Bs[1]) };

    float acc[4][4][4] = {};

    const int lr  = tid >> 3;
    const int lc4 = tid & 7;

    {
        #pragma unroll
        for (int it = 0; it < 4; ++it) {
            int r = lr + it * 32;
            uint32_t da = asA[0] + (uint32_t)(r * SM_STRIDE + lc4 * 4) * 4u;
            const float* sa = A + (size_t)(m0 + r) * DM + lc4 * 4;
            asm volatile("cp.async.cg.shared.global [%0], [%1], 16;"
                         :: "r"(da), "l"(sa));
            uint32_t db = asB[0] + (uint32_t)(r * SM_STRIDE + lc4 * 4) * 4u;
            const float* sb = W + (size_t)(n0 + r) * DM + lc4 * 4;
            asm volatile("cp.async.cg.shared.global [%0], [%1], 16;"
                         :: "r"(db), "l"(sb));
        }
        asm volatile("cp.async.commit_group;" ::: "memory");
    }

    const int NSTAGE = DM / 32;
    for (int s = 0; s < NSTAGE; ++s) {
        const int buf = s & 1;
        if (s + 1 < NSTAGE) {
            const int nb = buf ^ 1;
            const int k0 = (s + 1) * 32;
            #pragma unroll
            for (int it = 0; it < 4; ++it) {
                int r = lr + it * 32;
                uint32_t da = asA[nb] + (uint32_t)(r * SM_STRIDE + lc4 * 4) * 4u;
                const float* sa = A + (size_t)(m0 + r) * DM + k0 + lc4 * 4;
                asm volatile("cp.async.cg.shared.global [%0], [%1], 16;"
                             :: "r"(da), "l"(sa));
                uint32_t db = asB[nb] + (uint32_t)(r * SM_STRIDE + lc4 * 4) * 4u;
                const float* sb = W + (size_t)(n0 + r) * DM + k0 + lc4 * 4;
                asm volatile("cp.async.cg.shared.global [%0], [%1], 16;"
                             :: "r"(db), "l"(sb));
            }
            asm volatile("cp.async.commit_group;" ::: "memory");
            asm volatile("cp.async.wait_group %0;" :: "n"(1) : "memory");
        } else {
            asm volatile("cp.async.wait_group %0;" :: "n"(0) : "memory");
        }
        __syncthreads();

        const float* pa = As[buf];
        const float* pb = Bs[buf];
        #pragma unroll
        for (int kk = 0; kk < 4; ++kk) {
            const int kb = kk * 8;
            uint32_t af[4][4];
            #pragma unroll
            for (int mt = 0; mt < 4; ++mt) {
                int row = wM * 64 + mt * 16 + g;
                const float* base = pa + row * SM_STRIDE + kb + tg;
                af[mt][0] = f2tf(base[0]);
                af[mt][1] = f2tf(base[8 * SM_STRIDE]);
                af[mt][2] = f2tf(base[4]);
                af[mt][3] = f2tf(base[8 * SM_STRIDE + 4]);
            }
            uint32_t bf[4][2];
            #pragma unroll
            for (int nt = 0; nt < 4; ++nt) {
                int nn = wN * 32 + nt * 8 + g;
                const float* base = pb + nn * SM_STRIDE + kb + tg;
                bf[nt][0] = f2tf(base[0]);
                bf[nt][1] = f2tf(base[4]);
            }
            #pragma unroll
            for (int mt = 0; mt < 4; ++mt)
                #pragma unroll
                for (int nt = 0; nt < 4; ++nt)
                    mma_tf32(acc[mt][nt], af[mt], bf[nt]);
        }
        __syncthreads();
    }

    // Epilogue: store tf32-ROUNDED results (downstream mma reads them raw).
    #pragma unroll
    for (int mt = 0; mt < 4; ++mt) {
        int row = m0 + wM * 64 + mt * 16 + g;
        #pragma unroll
        for (int nt = 0; nt < 4; ++nt) {
            int col = n0 + wN * 32 + nt * 8 + tg * 2;
            float2 v0, v1;
            v0.x = __uint_as_float(f2tf(acc[mt][nt][0]));
            v0.y = __uint_as_float(f2tf(acc[mt][nt][1]));
            v1.x = __uint_as_float(f2tf(acc[mt][nt][2]));
            v1.y = __uint_as_float(f2tf(acc[mt][nt][3]));
            *(float2*)(C + (size_t)row * DM + col) = v0;
            *(float2*)(C + (size_t)(row + 8) * DM + col) = v1;
        }
    }
}

// ============================================================================
// tf32 mma.sync causal flash attention.
// Q-tile 128 x 64, 4 warps (32 rows each), K/V tiles 64 x 64 double-buffered.
// Q/K/V arrive pre-rounded to tf32 -> zero cvt on all operand loads.
// P is rounded once when written to Ss.
// ============================================================================
#define SW(r, c) (((r) << 6) + ((c) ^ (((r) & 7) << 3)))

__global__ void __launch_bounds__(128) attn_mma(const float* __restrict__ query)
{
    extern __shared__ __align__(16) float sm[];
    float* Kb[2] = { sm,           sm + 8192 };
    float* Vb[2] = { sm + 4096,    sm + 12288 };
    float* Ss    = sm + 16384;
    const uint32_t sK[2] = { smem_u32(Kb[0]), smem_u32(Kb[1]) };
    const uint32_t sV[2] = { smem_u32(Vb[0]), smem_u32(Vb[1]) };

    const int tid  = threadIdx.x;
    const int lane = tid & 31;
    const int wid  = tid >> 5;
    const int g    = lane >> 2;
    const int tg   = lane & 3;
    const int qt   = blockIdx.x;
    const int h    = blockIdx.y;
    const int n    = blockIdx.z;

    const size_t nbase = (size_t)n * LQL * DM;
    const int hcol = h * PP;
    const int KT = 2 * qt + 2;

    // ---- prefetch K/V tile 0 ----
    {
        const float* Kg = gK + nbase + hcol;
        const float* Vg = gV + nbase + hcol;
        #pragma unroll
        for (int i = 0; i < 8; ++i) {
            int idx = tid + i * 128;
            int r = idx >> 4, c = (idx & 15) << 2;
            uint32_t dst = (uint32_t)SW(r, c) * 4u;
            asm volatile("cp.async.cg.shared.global [%0], [%1], 16;"
                         :: "r"(sK[0] + dst), "l"(Kg + (size_t)r * DM + c));
            asm volatile("cp.async.cg.shared.global [%0], [%1], 16;"
                         :: "r"(sV[0] + dst), "l"(Vg + (size_t)r * DM + c));
        }
        asm volatile("cp.async.commit_group;" ::: "memory");
    }

    // ---- stage Q tile into Ss, then load register fragments (no cvt) ----
    {
        const float* Qg = gQ + nbase + (size_t)qt * 128 * DM + hcol;
        #pragma unroll
        for (int i = 0; i < 16; ++i) {
            int idx = tid + i * 128;
            int r = idx >> 4, c = (idx & 15) << 2;
            float4 v = *(const float4*)(Qg + (size_t)r * DM + c);
            *(float4*)(Ss + SW(r, c)) = v;
        }
    }
    __syncthreads();
    uint32_t qf[2][8][4];
    #pragma unroll
    for (int mb = 0; mb < 2; ++mb) {
        int r0 = wid * 32 + mb * 16 + g;
        #pragma unroll
        for (int ks = 0; ks < 8; ++ks) {
            qf[mb][ks][0] = ld_u32(Ss + SW(r0,     ks * 8 + tg));
            qf[mb][ks][1] = ld_u32(Ss + SW(r0 + 8, ks * 8 + tg));
            qf[mb][ks][2] = ld_u32(Ss + SW(r0,     ks * 8 + tg + 4));
            qf[mb][ks][3] = ld_u32(Ss + SW(r0 + 8, ks * 8 + tg + 4));
        }
    }
    __syncthreads();

    float o[2][8][4] = {};
    float mrow[2][2], lrow[2][2];
    #pragma unroll
    for (int a = 0; a < 2; ++a)
        #pragma unroll
        for (int b = 0; b < 2; ++b) { mrow[a][b] = -INFINITY; lrow[a][b] = 0.f; }

    for (int kt = 0; kt < KT; ++kt) {
        const int buf = kt & 1;
        if (kt + 1 < KT) {
            const float* Kg = gK + nbase + (size_t)(kt + 1) * 64 * DM + hcol;
            const float* Vg = gV + nbase + (size_t)(kt + 1) * 64 * DM + hcol;
            #pragma unroll
            for (int i = 0; i < 8; ++i) {
                int idx = tid + i * 128;
                int r = idx >> 4, c = (idx & 15) << 2;
                uint32_t dst = (uint32_t)SW(r, c) * 4u;
                asm volatile("cp.async.cg.shared.global [%0], [%1], 16;"
                             :: "r"(sK[buf ^ 1] + dst), "l"(Kg + (size_t)r * DM + c));
                asm volatile("cp.async.cg.shared.global [%0], [%1], 16;"
                             :: "r"(sV[buf ^ 1] + dst), "l"(Vg + (size_t)r * DM + c));
            }
            asm volatile("cp.async.commit_group;" ::: "memory");
            asm volatile("cp.async.wait_group %0;" :: "n"(1) : "memory");
        } else {
            asm volatile("cp.async.wait_group %0;" :: "n"(0) : "memory");
        }
        __syncthreads();

        const float* Ks = Kb[buf];
        const float* Vs = Vb[buf];

        // ---- S = Q K^T (K pre-rounded: raw loads) ----
        float s[2][8][4] = {};
        #pragma unroll
        for (int ks = 0; ks < 8; ++ks) {
            #pragma unroll
            for (int nb = 0; nb < 8; ++nb) {
                uint32_t bb[2];
                bb[0] = ld_u32(Ks + SW(nb * 8 + g, ks * 8 + tg));
                bb[1] = ld_u32(Ks + SW(nb * 8 + g, ks * 8 + tg + 4));
                mma_tf32(s[0][nb], qf[0][ks], bb);
                mma_tf32(s[1][nb], qf[1][ks], bb);
            }
        }

        // ---- mask + online softmax ----
        const bool tail = (kt >= 2 * qt);
        #pragma unroll
        for (int mb = 0; mb < 2; ++mb) {
            #pragma unroll
            for (int rr = 0; rr < 2; ++rr) {
                const int grow = qt * 128 + wid * 32 + mb * 16 + rr * 8 + g;
                float tm = -INFINITY;
                #pragma unroll
                for (int nb = 0; nb < 8; ++nb) {
                    float v0 = s[mb][nb][rr * 2 + 0] * 0.03125f;
                    float v1 = s[mb][nb][rr * 2 + 1] * 0.03125f;
                    if (tail) {
                        int c0 = kt * 64 + nb * 8 + tg * 2;
                        if (c0     > grow) v0 = -1e30f;
                        if (c0 + 1 > grow) v1 = -1e30f;
                    }
                    s[mb][nb][rr * 2 + 0] = v0;
                    s[mb][nb][rr * 2 + 1] = v1;
                    tm = fmaxf(tm, fmaxf(v0, v1));
                }
                tm = fmaxf(tm, __shfl_xor_sync(0xffffffffu, tm, 1));
                tm = fmaxf(tm, __shfl_xor_sync(0xffffffffu, tm, 2));
                float nm   = fmaxf(mrow[mb][rr], tm);
                float corr = __expf(mrow[mb][rr] - nm);
                mrow[mb][rr] = nm;
                float rs = 0.f;
                #pragma unroll
                for (int nb = 0; nb < 8; ++nb) {
                    float p0 = __expf(s[mb][nb][rr * 2 + 0] - nm);
                    float p1 = __expf(s[mb][nb][rr * 2 + 1] - nm);
                    s[mb][nb][rr * 2 + 0] = p0;
                    s[mb][nb][rr * 2 + 1] = p1;
                    rs += p0 + p1;
                }
                rs += __shfl_xor_sync(0xffffffffu, rs, 1);
                rs += __shfl_xor_sync(0xffffffffu, rs, 2);
                lrow[mb][rr] = lrow[mb][rr] * corr + rs;
                #pragma unroll
                for (int nb = 0; nb < 8; ++nb) {
                    o[mb][nb][rr * 2 + 0] *= corr;
                    o[mb][nb][rr * 2 + 1] *= corr;
                }
            }
        }

        // ---- store P to Ss, tf32-rounded at write ----
        #pragma unroll
        for (int mb = 0; mb < 2; ++mb) {
            int r0 = wid * 32 + mb * 16 + g;
            #pragma unroll
            for (int nb = 0; nb < 8; ++nb) {
                float2 w0, w1;
                w0.x = __uint_as_float(f2tf(s[mb][nb][0]));
                w0.y = __uint_as_float(f2tf(s[mb][nb][1]));
                w1.x = __uint_as_float(f2tf(s[mb][nb][2]));
                w1.y = __uint_as_float(f2tf(s[mb][nb][3]));
                *(float2*)(Ss + SW(r0,     nb * 8 + tg * 2)) = w0;
                *(float2*)(Ss + SW(r0 + 8, nb * 8 + tg * 2)) = w1;
            }
        }
        __syncthreads();

        // ---- O += P V (both pre-rounded: raw loads) ----
        #pragma unroll
        for (int ks = 0; ks < 8; ++ks) {
            uint32_t af[2][4];
            #pragma unroll
            for (int mb = 0; mb < 2; ++mb) {
                int r0 = wid * 32 + mb * 16 + g;
                af[mb][0] = ld_u32(Ss + SW(r0,     ks * 8 + tg));
                af[mb][1] = ld_u32(Ss + SW(r0 + 8, ks * 8 + tg));
                af[mb][2] = ld_u32(Ss + SW(r0,     ks * 8 + tg + 4));
                af[mb][3] = ld_u32(Ss + SW(r0 + 8, ks * 8 + tg + 4));
            }
            #pragma unroll
            for (int nb = 0; nb < 8; ++nb) {
                uint32_t bb[2];
                bb[0] = ld_u32(Vs + SW(ks * 8 + tg,     nb * 8 + g));
                bb[1] = ld_u32(Vs + SW(ks * 8 + tg + 4, nb * 8 + g));
                mma_tf32(o[0][nb], af[0], bb);
                mma_tf32(o[1][nb], af[1], bb);
            }
        }
        __syncthreads();
    }

    // ---- epilogue: normalize, add residual, write gRes ----
    #pragma unroll
    for (int mb = 0; mb < 2; ++mb) {
        #pragma unroll
        for (int rr = 0; rr < 2; ++rr) {
            float inv = 1.0f / lrow[mb][rr];
            int grow = qt * 128 + wid * 32 + mb * 16 + rr * 8 + g;
            size_t rowoff = nbase + (size_t)grow * DM + hcol;
            #pragma unroll
            for (int nb = 0; nb < 8; ++nb) {
                int c = nb * 8 + tg * 2;
                float2 qv = *(const float2*)(query + rowoff + c);
                float2 w;
                w.x = o[mb][nb][rr * 2 + 0] * inv + qv.x;
                w.y = o[mb][nb][rr * 2 + 1] * inv + qv.y;
                *(float2*)(gRes + rowoff + c) = w;
            }
        }
    }
}

// ---------------------------------------------------------------------------
// BatchNorm: deterministic two-stage column stats + fused normalize
// ---------------------------------------------------------------------------
__global__ void __launch_bounds__(256) colstats_partial()
{
    const int col   = blockIdx.x * 256 + threadIdx.x;
    const int chunk = blockIdx.y;
    const float* base = gRes + (size_t)chunk * 128 * DM + col;
    float s = 0.f, q = 0.f;
    #pragma unroll 8
    for (int r = 0; r < 128; ++r) {
        float v = base[(size_t)r * DM];
        s += v;
        q += v * v;
    }
    gPartS[chunk * DM + col] = s;
    gPartQ[chunk * DM + col] = q;
}

// 32 blocks x 256 threads: 32 cols/block, 8 threads/col (8 chunks each),
// then deterministic shfl tree over the 8 partials.
__global__ void __launch_bounds__(256) colstats_final(const float* __restrict__ gamma,
                                                      const float* __restrict__ beta)
{
    const int cidx = threadIdx.x & 31;          // column within block
    const int seg  = threadIdx.x >> 5;          // chunk segment 0..7
    const int col  = blockIdx.x * 32 + cidx;
    float s = 0.f, q = 0.f;
    #pragma unroll
    for (int c = 0; c < 8; ++c) {
        int chunk = seg * 8 + c;
        s += gPartS[chunk * DM + col];
        q += gPartQ[chunk * DM + col];
    }
    __shared__ float shS[8][33], shQ[8][33];
    shS[seg][cidx] = s;
    shQ[seg][cidx] = q;
    __syncthreads();
    if (seg == 0) {
        float ts = 0.f, tq = 0.f;
        #pragma unroll
        for (int i = 0; i < 8; ++i) { ts += shS[i][cidx]; tq += shQ[i][cidx]; }
        const float invn = 1.0f / (float)MROWS;
        float mean = ts * invn;
        float var  = tq * invn - mean * mean;
        float inv  = rsqrtf(var + EPSBN);
        float a    = gamma[col] * inv;
        gColA[col] = a;
        gColB[col] = beta[col] - mean * a;
    }
}

__global__ void __launch_bounds__(256) normalize_kernel(float* __restrict__ out)
{
    const size_t idx = (size_t)blockIdx.x * 256 + threadIdx.x;
    float4 v = ((const float4*)gRes)[idx];
    int col = (int)((idx * 4) & (DM - 1));
    float4 r;
    r.x = v.x * gColA[col + 0] + gColB[col + 0];
    r.y = v.y * gColA[col + 1] + gColB[col + 1];
    r.z = v.z * gColA[col + 2] + gColB[col + 2];
    r.w = v.w * gColA[col + 3] + gColB[col + 3];
    ((float4*)out)[idx] = r;
}

// ---------------------------------------------------------------------------
extern "C" void kernel_launch(void* const* d_in, const int* in_sizes, int n_in,
                              void* d_out, int out_size)
{
    const float* query = (const float*)d_in[0];
    const float* key   = (const float*)d_in[1];
    const float* Wq    = (const float*)d_in[2];
    const float* Wk    = (const float*)d_in[3];
    const float* Wv    = (const float*)d_in[4];
    const float* gamma = (const float*)d_in[5];
    const float* beta  = (const float*)d_in[6];
    float* out = (float*)d_out;

    const int gemm_smem = 4 * ABUF_F * 4;    // 73728
    cudaFuncSetAttribute(gemm_mma, cudaFuncAttributeMaxDynamicSharedMemorySize,
                         gemm_smem);
    dim3 gg(DM / 128, MROWS / 128, 3);
    gemm_mma<<<gg, 256, gemm_smem>>>(query, key, Wq, Wk, Wv);

    const int attn_smem = 24576 * 4;         // 96KB
    cudaFuncSetAttribute(attn_mma, cudaFuncAttributeMaxDynamicSharedMemorySize,
                         attn_smem);
    dim3 ga(LQL / 128, HH, NB);
    attn_mma<<<ga, 128, attn_smem>>>(query);

    colstats_partial<<<dim3(DM / 256, 64), 256>>>();
    colstats_final<<<DM / 32, 256>>>(gamma, beta);

    const int total_f4 = MROWS * DM / 4;
    normalize_kernel<<<total_f4 / 256, 256>>>(out);
}